// round 2
// baseline (speedup 1.0000x reference)
#include <cuda_runtime.h>
#include <math.h>

#define B_   32
#define N_   3136
#define D_   384
#define H_   8
#define C_   48
#define E_   1152            // 3*D
#define M_   (B_*N_)         // 100352
#define BH_  (B_*H_)         // 256

// ---- scratch (static device allocations; no runtime allocs) ----
__device__ float g_q[(size_t)BH_*C_*N_];     // (B,H,C,N)
__device__ float g_k[(size_t)BH_*C_*N_];
__device__ float g_v[(size_t)BH_*C_*N_];
__device__ float g_invq[BH_*C_];
__device__ float g_invk[BH_*C_];
__device__ float g_attn[(size_t)BH_*C_*C_];
__device__ float g_o[(size_t)M_*D_];         // (B,N,D)

// ============================================================
// K1: qkv = x @ qkv_w^T, scattered into q/k/v (B,H,C,N) layout
// C[m,e] = sum_k x[m,k] * w[e,k];  M=100352, E=1152, K=384
// Tiles: BM=64 (m), BN=64 (e), BK=16; 256 threads, 4x4 per thread
// ============================================================
__global__ __launch_bounds__(256) void k1_qkv(const float* __restrict__ x,
                                              const float* __restrict__ w) {
    __shared__ float As[16][64];   // [k][m]
    __shared__ float Bs[16][64];   // [k][e]
    const int tid = threadIdx.x;
    const int tx = tid & 15;       // -> m (n) direction
    const int ty = tid >> 4;       // -> e direction
    const int m0 = blockIdx.x * 64;
    const int e0 = blockIdx.y * 64;

    float acc[4][4];
    #pragma unroll
    for (int i = 0; i < 4; i++)
        #pragma unroll
        for (int j = 0; j < 4; j++) acc[i][j] = 0.f;

    const int lrow = tid >> 2;          // 0..63
    const int lc4  = (tid & 3) * 4;     // 0,4,8,12
    const float* aptr = x + (size_t)(m0 + lrow) * D_ + lc4;
    const float* bptr = w + (size_t)(e0 + lrow) * D_ + lc4;

    for (int kt = 0; kt < D_; kt += 16) {
        float4 av = *(const float4*)(aptr + kt);
        float4 bv = *(const float4*)(bptr + kt);
        As[lc4+0][lrow] = av.x; As[lc4+1][lrow] = av.y;
        As[lc4+2][lrow] = av.z; As[lc4+3][lrow] = av.w;
        Bs[lc4+0][lrow] = bv.x; Bs[lc4+1][lrow] = bv.y;
        Bs[lc4+2][lrow] = bv.z; Bs[lc4+3][lrow] = bv.w;
        __syncthreads();
        #pragma unroll
        for (int k = 0; k < 16; k++) {
            float4 a = *(const float4*)&As[k][tx*4];
            float4 b = *(const float4*)&Bs[k][ty*4];
            float ar[4] = {a.x, a.y, a.z, a.w};
            float br[4] = {b.x, b.y, b.z, b.w};
            #pragma unroll
            for (int i = 0; i < 4; i++)
                #pragma unroll
                for (int j = 0; j < 4; j++)
                    acc[i][j] += ar[i] * br[j];
        }
        __syncthreads();
    }

    // scatter epilogue: m = m0 + tx*4 + i  (n-contiguous, float4 over i)
    const int b = m0 / N_;                 // tile never straddles batch (3136%64==0)
    const int n = (m0 % N_) + tx * 4;
    #pragma unroll
    for (int j = 0; j < 4; j++) {
        int e = e0 + ty * 4 + j;
        int t = e / D_;
        int r = e % D_;
        int h = r / C_;
        int c = r % C_;
        float* dst = (t == 0) ? g_q : ((t == 1) ? g_k : g_v);
        float4 v4 = make_float4(acc[0][j], acc[1][j], acc[2][j], acc[3][j]);
        *(float4*)(dst + (size_t)((b * H_ + h) * C_ + c) * N_ + n) = v4;
    }
}

// ============================================================
// K2: inverse L2 norms of q,k rows (reduce over N). One warp/row.
// ============================================================
__global__ __launch_bounds__(256) void k2_norms() {
    const int gwarp = (blockIdx.x * blockDim.x + threadIdx.x) >> 5;
    const int lane  = threadIdx.x & 31;
    const int total = BH_ * C_;
    if (gwarp >= 2 * total) return;
    const bool is_q = (gwarp < total);
    const int row = is_q ? gwarp : (gwarp - total);
    const float* p = (is_q ? g_q : g_k) + (size_t)row * N_;
    float s = 0.f;
    for (int i = lane; i < N_; i += 32) { float v = p[i]; s += v * v; }
    #pragma unroll
    for (int off = 16; off; off >>= 1) s += __shfl_xor_sync(0xffffffffu, s, off);
    if (lane == 0) {
        float inv = 1.f / fmaxf(sqrtf(s), 1e-12f);
        (is_q ? g_invq : g_invk)[row] = inv;
    }
}

// ============================================================
// K3: attn[b,h] = softmax( (q_hat @ k_hat^T) * temp[h] )  (48x48, K=3136)
// one block per (b,h); stream 48x64 chunks; 3x3 per thread
// ============================================================
__global__ __launch_bounds__(256) void k3_attn(const float* __restrict__ temperature) {
    __shared__ float qs[48][68];
    __shared__ float ks[48][68];
    __shared__ float Ss[48][49];
    const int bh = blockIdx.x;
    const int h  = bh & (H_ - 1);
    const int tid = threadIdx.x;
    const int tx = tid & 15;    // -> d
    const int ty = tid >> 4;    // -> c
    const float* qp = g_q + (size_t)bh * C_ * N_;
    const float* kp = g_k + (size_t)bh * C_ * N_;

    float acc[3][3];
    #pragma unroll
    for (int i = 0; i < 3; i++)
        #pragma unroll
        for (int j = 0; j < 3; j++) acc[i][j] = 0.f;

    for (int n0 = 0; n0 < N_; n0 += 64) {
        #pragma unroll
        for (int it = 0; it < 3; it++) {
            int item = tid + it * 256;     // 0..767
            int row = item >> 4;           // 0..47
            int c4  = (item & 15) * 4;     // 0..60
            float4 a = *(const float4*)(qp + (size_t)row * N_ + n0 + c4);
            float4 b = *(const float4*)(kp + (size_t)row * N_ + n0 + c4);
            *(float4*)&qs[row][c4] = a;
            *(float4*)&ks[row][c4] = b;
        }
        __syncthreads();
        #pragma unroll 4
        for (int nn = 0; nn < 64; nn++) {
            float qr[3], kr[3];
            #pragma unroll
            for (int i = 0; i < 3; i++) qr[i] = qs[ty * 3 + i][nn];
            #pragma unroll
            for (int j = 0; j < 3; j++) kr[j] = ks[tx * 3 + j][nn];
            #pragma unroll
            for (int i = 0; i < 3; i++)
                #pragma unroll
                for (int j = 0; j < 3; j++)
                    acc[i][j] += qr[i] * kr[j];
        }
        __syncthreads();
    }

    const float temp = temperature[h];
    #pragma unroll
    for (int i = 0; i < 3; i++) {
        int c = ty * 3 + i;
        float iq = g_invq[bh * C_ + c] * temp;
        #pragma unroll
        for (int j = 0; j < 3; j++) {
            int d = tx * 3 + j;
            Ss[c][d] = acc[i][j] * iq * g_invk[bh * C_ + d];
        }
    }
    __syncthreads();

    if (tid < C_) {
        const int c = tid;
        float mx = -INFINITY;
        for (int d = 0; d < C_; d++) mx = fmaxf(mx, Ss[c][d]);
        float sum = 0.f;
        for (int d = 0; d < C_; d++) sum += expf(Ss[c][d] - mx);
        float inv = 1.f / sum;
        float* out = g_attn + ((size_t)bh * C_ + c) * C_;
        for (int d = 0; d < C_; d++) out[d] = expf(Ss[c][d] - mx) * inv;
    }
}

// ============================================================
// K4: out = attn @ v, written directly to (B,N,D) layout.
// one thread per token n; attn tile in smem (broadcast reads)
// ============================================================
__global__ __launch_bounds__(256) void k4_av() {
    __shared__ float As[48][49];
    const int bh = blockIdx.y;
    const int b = bh >> 3, h = bh & 7;
    const int tid = threadIdx.x;
    for (int i = tid; i < C_ * C_; i += 256)
        As[i / C_][i % C_] = g_attn[(size_t)bh * C_ * C_ + i];
    __syncthreads();

    const int n = blockIdx.x * 256 + tid;
    if (n >= N_) return;
    const float* vp = g_v + (size_t)bh * C_ * N_ + n;
    float acc[C_];
    #pragma unroll
    for (int c = 0; c < C_; c++) acc[c] = 0.f;
    for (int d = 0; d < C_; d++) {
        float vd = vp[(size_t)d * N_];
        #pragma unroll
        for (int c = 0; c < C_; c++) acc[c] += As[c][d] * vd;
    }
    float* op = g_o + ((size_t)b * N_ + n) * D_ + h * C_;
    #pragma unroll
    for (int c = 0; c < C_; c += 4)
        *(float4*)(op + c) = make_float4(acc[c], acc[c+1], acc[c+2], acc[c+3]);
}

// ============================================================
// K5: y = o @ proj_w^T + proj_b ; M=100352, E=384, K=384
// same tiling as K1, row-major coalesced epilogue
// ============================================================
__global__ __launch_bounds__(256) void k5_proj(const float* __restrict__ pw,
                                               const float* __restrict__ pb,
                                               float* __restrict__ y) {
    __shared__ float As[16][64];   // [k][m]
    __shared__ float Bs[16][64];   // [k][e]
    const int tid = threadIdx.x;
    const int tx = tid & 15;       // -> e
    const int ty = tid >> 4;       // -> m
    const int m0 = blockIdx.x * 64;
    const int e0 = blockIdx.y * 64;

    float acc[4][4];
    #pragma unroll
    for (int i = 0; i < 4; i++)
        #pragma unroll
        for (int j = 0; j < 4; j++) acc[i][j] = 0.f;

    const int lrow = tid >> 2;
    const int lc4  = (tid & 3) * 4;
    const float* aptr = g_o + (size_t)(m0 + lrow) * D_ + lc4;
    const float* bptr = pw  + (size_t)(e0 + lrow) * D_ + lc4;

    for (int kt = 0; kt < D_; kt += 16) {
        float4 av = *(const float4*)(aptr + kt);
        float4 bv = *(const float4*)(bptr + kt);
        As[lc4+0][lrow] = av.x; As[lc4+1][lrow] = av.y;
        As[lc4+2][lrow] = av.z; As[lc4+3][lrow] = av.w;
        Bs[lc4+0][lrow] = bv.x; Bs[lc4+1][lrow] = bv.y;
        Bs[lc4+2][lrow] = bv.z; Bs[lc4+3][lrow] = bv.w;
        __syncthreads();
        #pragma unroll
        for (int k = 0; k < 16; k++) {
            float4 a = *(const float4*)&As[k][ty*4];   // m
            float4 b = *(const float4*)&Bs[k][tx*4];   // e
            float ar[4] = {a.x, a.y, a.z, a.w};
            float br[4] = {b.x, b.y, b.z, b.w};
            #pragma unroll
            for (int i = 0; i < 4; i++)
                #pragma unroll
                for (int j = 0; j < 4; j++)
                    acc[i][j] += ar[i] * br[j];
        }
        __syncthreads();
    }

    const int m = m0 + ty * 4;
    float4 bias = *(const float4*)(pb + e0 + tx * 4);
    #pragma unroll
    for (int i = 0; i < 4; i++) {
        float4 o4 = make_float4(acc[i][0] + bias.x, acc[i][1] + bias.y,
                                acc[i][2] + bias.z, acc[i][3] + bias.w);
        *(float4*)(y + (size_t)(m + i) * D_ + e0 + tx * 4) = o4;
    }
}

// ============================================================
extern "C" void kernel_launch(void* const* d_in, const int* in_sizes, int n_in,
                              void* d_out, int out_size) {
    const float* x           = (const float*)d_in[0];
    const float* qkv_w       = (const float*)d_in[1];
    const float* temperature = (const float*)d_in[2];
    const float* proj_w      = (const float*)d_in[3];
    const float* proj_b      = (const float*)d_in[4];
    float* y = (float*)d_out;

    k1_qkv<<<dim3(M_ / 64, E_ / 64), 256>>>(x, qkv_w);          // 1568 x 18
    k2_norms<<<(2 * BH_ * C_ + 7) / 8, 256>>>();                // 3072 blocks
    k3_attn<<<BH_, 256>>>(temperature);                         // 256 blocks
    k4_av<<<dim3((N_ + 255) / 256, BH_), 256>>>();              // 13 x 256
    k5_proj<<<dim3(M_ / 64, D_ / 64), 256>>>(proj_w, proj_b, y);// 1568 x 6
}

// round 4
// speedup vs baseline: 2.4280x; 2.4280x over previous
#include <cuda_runtime.h>
#include <cuda_bf16.h>
#include <math.h>
#include <stdint.h>

#define B_   32
#define N_   3136
#define D_   384
#define H_   8
#define C_   48
#define E_   1152            // 3*D
#define M_   (B_*N_)         // 100352
#define BH_  (B_*H_)         // 256

// ---- scratch (static device allocations; no runtime allocs) ----
__device__ float g_q[(size_t)BH_*C_*N_];     // (B,H,C,N)
__device__ float g_k[(size_t)BH_*C_*N_];
__device__ float g_v[(size_t)BH_*C_*N_];
__device__ float g_invq[BH_*C_];
__device__ float g_invk[BH_*C_];
__device__ float g_attn[(size_t)BH_*C_*C_];
__device__ float g_o[(size_t)M_*D_];         // (B,N,D)

// ============================================================
// warp-mma helpers (baseline PTX, legal on target sm_103)
// ============================================================
__device__ __forceinline__ uint32_t smem_u32(const void* p) {
    uint32_t a;
    asm("{ .reg .u64 t; cvta.to.shared.u64 t, %1; cvt.u32.u64 %0, t; }" : "=r"(a) : "l"(p));
    return a;
}

__device__ __forceinline__ void ldsm4(uint32_t* r, uint32_t a) {
    asm volatile("ldmatrix.sync.aligned.m8n8.x4.shared.b16 {%0,%1,%2,%3}, [%4];"
                 : "=r"(r[0]), "=r"(r[1]), "=r"(r[2]), "=r"(r[3]) : "r"(a));
}

__device__ __forceinline__ void mma16816(float* c, const uint32_t* a,
                                         uint32_t b0, uint32_t b1) {
    asm volatile("mma.sync.aligned.m16n8k16.row.col.f32.bf16.bf16.f32 "
                 "{%0,%1,%2,%3}, {%4,%5,%6,%7}, {%8,%9}, {%0,%1,%2,%3};"
                 : "+f"(c[0]), "+f"(c[1]), "+f"(c[2]), "+f"(c[3])
                 : "r"(a[0]), "r"(a[1]), "r"(a[2]), "r"(a[3]), "r"(b0), "r"(b1));
}

// smem tile: 128 rows x 128B; row = [32 bf16 hi | 32 bf16 lo], SW128 swizzle
#define TILE_BYTES 16384
#define AH_OFF 0
#define BH_OFF TILE_BYTES
#define SMEM_BYTES (2*TILE_BYTES)

__device__ __forceinline__ uint32_t sw_addr(uint32_t base, int row, int unit) {
    return base + row * 128 + (((unit) ^ (row & 7)) << 4);
}

// split fp32 float4 -> hi/lo bf16x2 pairs, store into packed tile row
__device__ __forceinline__ void store_hilo(uint32_t tile, int row, int q4, float4 v) {
    __nv_bfloat162 h0 = __floats2bfloat162_rn(v.x, v.y);
    __nv_bfloat162 h1 = __floats2bfloat162_rn(v.z, v.w);
    float2 f0 = __bfloat1622float2(h0);
    float2 f1 = __bfloat1622float2(h1);
    __nv_bfloat162 l0 = __floats2bfloat162_rn(v.x - f0.x, v.y - f0.y);
    __nv_bfloat162 l1 = __floats2bfloat162_rn(v.z - f1.x, v.w - f1.y);
    uint32_t uh0 = *reinterpret_cast<uint32_t*>(&h0);
    uint32_t uh1 = *reinterpret_cast<uint32_t*>(&h1);
    uint32_t ul0 = *reinterpret_cast<uint32_t*>(&l0);
    uint32_t ul1 = *reinterpret_cast<uint32_t*>(&l1);
    // hi at units 0..3, lo at units 4..7; 8-byte sub-stores within 16B unit
    uint32_t ah = sw_addr(tile, row, (q4 >> 1)) + (q4 & 1) * 8;
    uint32_t al = sw_addr(tile, row, (q4 >> 1) + 4) + (q4 & 1) * 8;
    asm volatile("st.shared.v2.b32 [%0], {%1,%2};" :: "r"(ah), "r"(uh0), "r"(uh1) : "memory");
    asm volatile("st.shared.v2.b32 [%0], {%1,%2};" :: "r"(al), "r"(ul0), "r"(ul1) : "memory");
}

// C[128m x 128e] = A[128 x 384] * B[128 x 384]^T, bf16 hi/lo 3-product split.
// 8 warps: wm = wid&3 (32-row strip), wn = wid>>2 (64-col strip).
__device__ __forceinline__ void gemm_main(const float* __restrict__ A,
                                          const float* __restrict__ Bw,
                                          uint32_t sb, float acc[2][8][4]) {
    const int tid = threadIdx.x;
    const int lane = tid & 31;
    const int wid = tid >> 5;
    const int wm = wid & 3, wn = wid >> 2;
    const int lr = lane & 15, lu = lane >> 4;

    // per-thread ldmatrix rows
    int rA0 = wm * 32 + lr;            // mt=0 rows; mt=1 adds 16
    int rB0 = wn * 64 + lr;            // nb adds 16

    for (int kt = 0; kt < 12; kt++) {
        const int k0 = kt * 32;
        #pragma unroll
        for (int t = 0; t < 4; t++) {
            int item = tid + t * 256;    // 0..1023
            int row = item >> 3;         // 0..127
            int q4  = item & 7;          // float4 index within 32 floats
            float4 va = *(const float4*)(A  + (size_t)row * D_ + k0 + q4 * 4);
            float4 vb = *(const float4*)(Bw + (size_t)row * D_ + k0 + q4 * 4);
            store_hilo(sb + AH_OFF, row, q4, va);
            store_hilo(sb + BH_OFF, row, q4, vb);
        }
        __syncthreads();

        #pragma unroll
        for (int ks = 0; ks < 2; ks++) {
            uint32_t ah[2][4], al[2][4];
            #pragma unroll
            for (int mt = 0; mt < 2; mt++) {
                int r = rA0 + mt * 16;
                ldsm4(ah[mt], sw_addr(sb + AH_OFF, r, ks * 2 + lu));
                ldsm4(al[mt], sw_addr(sb + AH_OFF, r, 4 + ks * 2 + lu));
            }
            #pragma unroll
            for (int nb = 0; nb < 4; nb++) {
                uint32_t bh[4], bl[4];
                int r = rB0 + nb * 16;
                ldsm4(bh, sw_addr(sb + BH_OFF, r, ks * 2 + lu));
                ldsm4(bl, sw_addr(sb + BH_OFF, r, 4 + ks * 2 + lu));
                #pragma unroll
                for (int mt = 0; mt < 2; mt++) {
                    #pragma unroll
                    for (int hf = 0; hf < 2; hf++) {
                        float* c = acc[mt][nb * 2 + hf];
                        mma16816(c, ah[mt], bh[hf], bh[2 + hf]);
                        mma16816(c, ah[mt], bl[hf], bl[2 + hf]);
                        mma16816(c, al[mt], bh[hf], bh[2 + hf]);
                    }
                }
            }
        }
        __syncthreads();
    }
}

// ============================================================
// K1: qkv GEMM, scatter into q/k/v (B,H,C,N). grid (9, 784)
// ============================================================
__global__ __launch_bounds__(256) void k1_mma(const float* __restrict__ x,
                                              const float* __restrict__ w) {
    __shared__ __align__(128) char smem[SMEM_BYTES];
    uint32_t sb = smem_u32(smem);
    float acc[2][8][4];
    #pragma unroll
    for (int i = 0; i < 2; i++)
        #pragma unroll
        for (int j = 0; j < 8; j++)
            #pragma unroll
            for (int kk = 0; kk < 4; kk++) acc[i][j][kk] = 0.f;

    const int e0 = blockIdx.x * 128;
    const int m0 = blockIdx.y * 128;
    gemm_main(x + (size_t)m0 * D_, w + (size_t)e0 * D_, sb, acc);

    const int tid = threadIdx.x, lane = tid & 31, wid = tid >> 5;
    const int wm = wid & 3, wn = wid >> 2;
    const int lq = lane >> 2, le = (lane & 3) * 2;
    const int t = e0 / D_;              // uniform per block (384 % 128 == 0)
    float* dst = (t == 0) ? g_q : ((t == 1) ? g_k : g_v);
    const int ebase = e0 - t * D_ + wn * 64 + le;

    #pragma unroll
    for (int mt = 0; mt < 2; mt++) {
        int rowl = wm * 32 + mt * 16 + lq;
        #pragma unroll
        for (int rr = 0; rr < 2; rr++) {
            int m = m0 + rowl + rr * 8;
            int bb = m / N_;
            int n = m - bb * N_;
            #pragma unroll
            for (int nt = 0; nt < 8; nt++) {
                int el = ebase + nt * 8;
                int h = el / C_;
                int c = el - h * C_;
                float* p = dst + ((size_t)(bb * H_ + h) * C_ + c) * N_ + n;
                p[0]  = acc[mt][nt][rr * 2 + 0];
                p[N_] = acc[mt][nt][rr * 2 + 1];   // c+1 < 48 (le even)
            }
        }
    }
}

// ============================================================
// K5: y = o @ proj_w^T + proj_b. grid (3, 784)
// ============================================================
__global__ __launch_bounds__(256) void k5_mma(const float* __restrict__ pw,
                                              const float* __restrict__ pb,
                                              float* __restrict__ y) {
    __shared__ __align__(128) char smem[SMEM_BYTES];
    uint32_t sb = smem_u32(smem);
    float acc[2][8][4];
    #pragma unroll
    for (int i = 0; i < 2; i++)
        #pragma unroll
        for (int j = 0; j < 8; j++)
            #pragma unroll
            for (int kk = 0; kk < 4; kk++) acc[i][j][kk] = 0.f;

    const int e0 = blockIdx.x * 128;
    const int m0 = blockIdx.y * 128;
    gemm_main(g_o + (size_t)m0 * D_, pw + (size_t)e0 * D_, sb, acc);

    const int tid = threadIdx.x, lane = tid & 31, wid = tid >> 5;
    const int wm = wid & 3, wn = wid >> 2;
    const int lq = lane >> 2, le = (lane & 3) * 2;

    #pragma unroll
    for (int mt = 0; mt < 2; mt++) {
        int rowl = wm * 32 + mt * 16 + lq;
        #pragma unroll
        for (int rr = 0; rr < 2; rr++) {
            int m = m0 + rowl + rr * 8;
            float* yp = y + (size_t)m * D_ + e0;
            #pragma unroll
            for (int nt = 0; nt < 8; nt++) {
                int col = wn * 64 + nt * 8 + le;
                float2 o;
                o.x = acc[mt][nt][rr * 2 + 0] + pb[e0 + col];
                o.y = acc[mt][nt][rr * 2 + 1] + pb[e0 + col + 1];
                *(float2*)(yp + col) = o;
            }
        }
    }
}

// ============================================================
// K2: inverse L2 norms of q,k rows (reduce over N). One warp/row.
// ============================================================
__global__ __launch_bounds__(256) void k2_norms() {
    const int gwarp = (blockIdx.x * blockDim.x + threadIdx.x) >> 5;
    const int lane  = threadIdx.x & 31;
    const int total = BH_ * C_;
    if (gwarp >= 2 * total) return;
    const bool is_q = (gwarp < total);
    const int row = is_q ? gwarp : (gwarp - total);
    const float* p = (is_q ? g_q : g_k) + (size_t)row * N_;
    float s = 0.f;
    for (int i = lane; i < N_; i += 32) { float v = p[i]; s += v * v; }
    #pragma unroll
    for (int off = 16; off; off >>= 1) s += __shfl_xor_sync(0xffffffffu, s, off);
    if (lane == 0) {
        float inv = 1.f / fmaxf(sqrtf(s), 1e-12f);
        (is_q ? g_invq : g_invk)[row] = inv;
    }
}

// ============================================================
// K3: attn[b,h] = softmax( (q_hat @ k_hat^T) * temp[h] )  (48x48, K=3136)
// ============================================================
__global__ __launch_bounds__(256) void k3_attn(const float* __restrict__ temperature) {
    __shared__ float qs[48][68];
    __shared__ float ks[48][68];
    __shared__ float Ss[48][49];
    const int bh = blockIdx.x;
    const int h  = bh & (H_ - 1);
    const int tid = threadIdx.x;
    const int tx = tid & 15;    // -> d
    const int ty = tid >> 4;    // -> c
    const float* qp = g_q + (size_t)bh * C_ * N_;
    const float* kp = g_k + (size_t)bh * C_ * N_;

    float acc[3][3];
    #pragma unroll
    for (int i = 0; i < 3; i++)
        #pragma unroll
        for (int j = 0; j < 3; j++) acc[i][j] = 0.f;

    for (int n0 = 0; n0 < N_; n0 += 64) {
        #pragma unroll
        for (int it = 0; it < 3; it++) {
            int item = tid + it * 256;
            int row = item >> 4;
            int c4  = (item & 15) * 4;
            float4 a = *(const float4*)(qp + (size_t)row * N_ + n0 + c4);
            float4 b = *(const float4*)(kp + (size_t)row * N_ + n0 + c4);
            *(float4*)&qs[row][c4] = a;
            *(float4*)&ks[row][c4] = b;
        }
        __syncthreads();
        #pragma unroll 4
        for (int nn = 0; nn < 64; nn++) {
            float qr[3], kr[3];
            #pragma unroll
            for (int i = 0; i < 3; i++) qr[i] = qs[ty * 3 + i][nn];
            #pragma unroll
            for (int j = 0; j < 3; j++) kr[j] = ks[tx * 3 + j][nn];
            #pragma unroll
            for (int i = 0; i < 3; i++)
                #pragma unroll
                for (int j = 0; j < 3; j++)
                    acc[i][j] += qr[i] * kr[j];
        }
        __syncthreads();
    }

    const float temp = temperature[h];
    #pragma unroll
    for (int i = 0; i < 3; i++) {
        int c = ty * 3 + i;
        float iq = g_invq[bh * C_ + c] * temp;
        #pragma unroll
        for (int j = 0; j < 3; j++) {
            int d = tx * 3 + j;
            Ss[c][d] = acc[i][j] * iq * g_invk[bh * C_ + d];
        }
    }
    __syncthreads();

    if (tid < C_) {
        const int c = tid;
        float mx = -INFINITY;
        for (int d = 0; d < C_; d++) mx = fmaxf(mx, Ss[c][d]);
        float sum = 0.f;
        for (int d = 0; d < C_; d++) sum += expf(Ss[c][d] - mx);
        float inv = 1.f / sum;
        float* out = g_attn + ((size_t)bh * C_ + c) * C_;
        for (int d = 0; d < C_; d++) out[d] = expf(Ss[c][d] - mx) * inv;
    }
}

// ============================================================
// K4: out = attn @ v, written to (B,N,D) layout (fp32 for k5).
// ============================================================
__global__ __launch_bounds__(256) void k4_av() {
    __shared__ float As[48][49];
    const int bh = blockIdx.y;
    const int b = bh >> 3, h = bh & 7;
    const int tid = threadIdx.x;
    for (int i = tid; i < C_ * C_; i += 256)
        As[i / C_][i % C_] = g_attn[(size_t)bh * C_ * C_ + i];
    __syncthreads();

    const int n = blockIdx.x * 256 + tid;
    if (n >= N_) return;
    const float* vp = g_v + (size_t)bh * C_ * N_ + n;
    float acc[C_];
    #pragma unroll
    for (int c = 0; c < C_; c++) acc[c] = 0.f;
    for (int d = 0; d < C_; d++) {
        float vd = vp[(size_t)d * N_];
        #pragma unroll
        for (int c = 0; c < C_; c++) acc[c] += As[c][d] * vd;
    }
    float* op = g_o + ((size_t)b * N_ + n) * D_ + h * C_;
    #pragma unroll
    for (int c = 0; c < C_; c += 4)
        *(float4*)(op + c) = make_float4(acc[c], acc[c+1], acc[c+2], acc[c+3]);
}

// ============================================================
extern "C" void kernel_launch(void* const* d_in, const int* in_sizes, int n_in,
                              void* d_out, int out_size) {
    const float* x           = (const float*)d_in[0];
    const float* qkv_w       = (const float*)d_in[1];
    const float* temperature = (const float*)d_in[2];
    const float* proj_w      = (const float*)d_in[3];
    const float* proj_b      = (const float*)d_in[4];
    float* y = (float*)d_out;

    k1_mma<<<dim3(E_ / 128, M_ / 128), 256>>>(x, qkv_w);        // (9, 784)
    k2_norms<<<(2 * BH_ * C_ + 7) / 8, 256>>>();
    k3_attn<<<BH_, 256>>>(temperature);
    k4_av<<<dim3((N_ + 255) / 256, BH_), 256>>>();
    k5_mma<<<dim3(D_ / 128, M_ / 128), 256>>>(proj_w, proj_b, y); // (3, 784)
}